// round 4
// baseline (speedup 1.0000x reference)
#include <cuda_runtime.h>
#include <cstdint>

// Problem constants
#define BB 64
#define SS 512
#define HH 768
#define EE 128
#define TT_ 4
#define NT 5
#define H4 192   // H/4 float4 lanes

// Scratch (no allocs allowed)
__device__ float g_rowcoef[BB * SS * 8];   // {at0..at4, ac, 0, 0} per (b,s)

// ---------------------------------------------------------------------------
// P: per-batch coefficient build. One block per batch b (512 threads, one per
// flat (e,t)). Histogram into smem via atomics, then write 512 rows x 8 floats.
// ---------------------------------------------------------------------------
__global__ void __launch_bounds__(512) rowcoef_kernel(
    const int* __restrict__ ent_tokens,     // [E,T]
    const int* __restrict__ types,          // [B,E]
    const float* __restrict__ conf) {       // [B,E]
    __shared__ float sm[SS * 6];
    int b = blockIdx.x;
    int tid = threadIdx.x;                  // 0..511 == flat (e,t)

#pragma unroll
    for (int j = 0; j < 6; j++) sm[tid + j * SS] = 0.f;
    __syncthreads();

    int tok = ent_tokens[tid];
    int e = tid >> 2;
    int ty = types[b * EE + e];
    float c = conf[b * EE + e];
    atomicAdd(&sm[tok * 6 + ty], 1.f);
    atomicAdd(&sm[tok * 6 + 5], c);
    __syncthreads();

    float4* o = reinterpret_cast<float4*>(&g_rowcoef[((size_t)b * SS + tid) * 8]);
    o[0] = make_float4(sm[tid * 6 + 0], sm[tid * 6 + 1], sm[tid * 6 + 2], sm[tid * 6 + 3]);
    o[1] = make_float4(sm[tid * 6 + 4], sm[tid * 6 + 5], 0.f, 0.f);
}

// ---------------------------------------------------------------------------
// Task body, inlined twice per loop iteration for MLP=2.
// ---------------------------------------------------------------------------
struct Tables {
    float4 ttc[NT];
    float4 cw4;
};

__device__ __forceinline__ void process_task(
    int idx, int h,
    const float* __restrict__ hidden,
    const int* __restrict__ ent_tokens,
    const Tables& tb,
    float* __restrict__ out_enh,
    float* __restrict__ out_emb) {
    int b = idx / (SS + EE);
    int r = idx - b * (SS + EE);
    const float* hb = hidden + (size_t)b * SS * HH;

    if (r < SS) {
        int s = r;
        const float4* cf = reinterpret_cast<const float4*>(
            &g_rowcoef[((size_t)b * SS + s) * 8]);
        float4 c0 = __ldg(cf);
        float4 c1 = __ldg(cf + 1);
        float4 v = *reinterpret_cast<const float4*>(hb + (size_t)s * HH + h);
        float a0 = c0.x, a1 = c0.y, a2 = c0.z, a3 = c0.w, a4 = c1.x, ac = c1.y;
        v.x += a0 * tb.ttc[0].x + a1 * tb.ttc[1].x + a2 * tb.ttc[2].x + a3 * tb.ttc[3].x + a4 * tb.ttc[4].x + ac * tb.cw4.x;
        v.y += a0 * tb.ttc[0].y + a1 * tb.ttc[1].y + a2 * tb.ttc[2].y + a3 * tb.ttc[3].y + a4 * tb.ttc[4].y + ac * tb.cw4.y;
        v.z += a0 * tb.ttc[0].z + a1 * tb.ttc[1].z + a2 * tb.ttc[2].z + a3 * tb.ttc[3].z + a4 * tb.ttc[4].z + ac * tb.cw4.z;
        v.w += a0 * tb.ttc[0].w + a1 * tb.ttc[1].w + a2 * tb.ttc[2].w + a3 * tb.ttc[3].w + a4 * tb.ttc[4].w + ac * tb.cw4.w;
        *reinterpret_cast<float4*>(out_enh + ((size_t)b * SS + s) * HH + h) = v;
    } else {
        int e = r - SS;
        float4 acc = make_float4(0.f, 0.f, 0.f, 0.f);
        float a0 = 0.f, a1 = 0.f, a2 = 0.f, a3 = 0.f, a4 = 0.f, ac = 0.f;
        int sidx[TT_];
#pragma unroll
        for (int t = 0; t < TT_; t++) sidx[t] = __ldg(&ent_tokens[e * TT_ + t]);
#pragma unroll
        for (int t = 0; t < TT_; t++) {
            int s = sidx[t];
            const float4* cf = reinterpret_cast<const float4*>(
                &g_rowcoef[((size_t)b * SS + s) * 8]);
            float4 c0 = __ldg(cf);
            float4 c1 = __ldg(cf + 1);
            a0 += c0.x; a1 += c0.y; a2 += c0.z; a3 += c0.w; a4 += c1.x; ac += c1.y;
            float4 v = *reinterpret_cast<const float4*>(hb + (size_t)s * HH + h);
            acc.x += v.x; acc.y += v.y; acc.z += v.z; acc.w += v.w;
        }
        acc.x += a0 * tb.ttc[0].x + a1 * tb.ttc[1].x + a2 * tb.ttc[2].x + a3 * tb.ttc[3].x + a4 * tb.ttc[4].x + ac * tb.cw4.x;
        acc.y += a0 * tb.ttc[0].y + a1 * tb.ttc[1].y + a2 * tb.ttc[2].y + a3 * tb.ttc[3].y + a4 * tb.ttc[4].y + ac * tb.cw4.y;
        acc.z += a0 * tb.ttc[0].z + a1 * tb.ttc[1].z + a2 * tb.ttc[2].z + a3 * tb.ttc[3].z + a4 * tb.ttc[4].z + ac * tb.cw4.z;
        acc.w += a0 * tb.ttc[0].w + a1 * tb.ttc[1].w + a2 * tb.ttc[2].w + a3 * tb.ttc[3].w + a4 * tb.ttc[4].w + ac * tb.cw4.w;
        acc.x *= 0.25f; acc.y *= 0.25f; acc.z *= 0.25f; acc.w *= 0.25f;
        *reinterpret_cast<float4*>(out_emb + ((size_t)b * EE + e) * HH + h) = acc;
    }
}

// ---------------------------------------------------------------------------
// Fused main kernel (persistent grid-stride, 2 tasks per iteration for MLP).
// Task list per batch b: 512 enhance rows then 128 emb tasks (computed from
// hidden directly — gather reads hit L2 since the same batch's rows were just
// streamed by nearby enhance tasks).
// ---------------------------------------------------------------------------
__global__ void __launch_bounds__(H4) fused_kernel(
    const float* __restrict__ hidden,       // [B,S,H]
    const int* __restrict__ ent_tokens,     // [E,T]
    const float* __restrict__ type_table,   // [NT,H]
    const float* __restrict__ conf_w,       // [H]
    const float* __restrict__ conf_b,       // [H]
    float* __restrict__ out_enh,            // [B,S,H]
    float* __restrict__ out_emb) {          // [B,E,H]
    int tid = threadIdx.x;                  // 0..191
    int h = tid * 4;

    float4 cb4 = *reinterpret_cast<const float4*>(conf_b + h);
    Tables tb;
    tb.cw4 = *reinterpret_cast<const float4*>(conf_w + h);
#pragma unroll
    for (int ty = 0; ty < NT; ty++) {
        float4 v = *reinterpret_cast<const float4*>(type_table + ty * HH + h);
        tb.ttc[ty] = make_float4(v.x + cb4.x, v.y + cb4.y, v.z + cb4.z, v.w + cb4.w);
    }

    const int NTASK = BB * (SS + EE);
    int base = blockIdx.x * 2;
    int stride = gridDim.x * 2;
    for (int idx = base; idx < NTASK; idx += stride) {
        process_task(idx, h, hidden, ent_tokens, tb, out_enh, out_emb);
        if (idx + 1 < NTASK)
            process_task(idx + 1, h, hidden, ent_tokens, tb, out_enh, out_emb);
    }
}

// ---------------------------------------------------------------------------
// Inputs in metadata order:
// 0 hidden_states (B,S,H) f32 | 1 entity_types (B,E) i32 | 2 entity_confidences (B,E) f32
// 3 ent_tokens (E,T) i32 | 4 type_table (NT,H) f32 | 5 conf_w (1,H) f32 | 6 conf_b (H) f32
// Output: enhanced (B,S,H) then entity_embeddings (B,E,H), concatenated.
// ---------------------------------------------------------------------------
extern "C" void kernel_launch(void* const* d_in, const int* in_sizes, int n_in,
                              void* d_out, int out_size) {
    const float* hidden   = (const float*)d_in[0];
    const int*   types    = (const int*)d_in[1];
    const float* conf     = (const float*)d_in[2];
    const int*   ent_tok  = (const int*)d_in[3];
    const float* ttab     = (const float*)d_in[4];
    const float* conf_w   = (const float*)d_in[5];
    const float* conf_b   = (const float*)d_in[6];

    float* out_enh = (float*)d_out;
    float* out_emb = out_enh + (size_t)BB * SS * HH;

    rowcoef_kernel<<<BB, 512>>>(ent_tok, types, conf);
    fused_kernel<<<888, H4>>>(hidden, ent_tok, ttab, conf_w, conf_b,
                              out_enh, out_emb);
}

// round 5
// speedup vs baseline: 1.4699x; 1.4699x over previous
#include <cuda_runtime.h>
#include <cstdint>

// Problem constants
#define BB 64
#define SS 512
#define HH 768
#define EE 128
#define TT_ 4
#define NT 5
#define H4 192   // H/4 float4 lanes

// Scratch (no allocs allowed)
__device__ float g_rowcoef[BB * SS * 8];   // {at0..at4, ac, 0, 0} per (b,s)

// ---------------------------------------------------------------------------
// P: per-batch coefficient build. One block per batch b (512 threads, one per
// flat (e,t)). Histogram into smem via atomics, then write 512 rows x 8 floats.
// ---------------------------------------------------------------------------
__global__ void __launch_bounds__(512) rowcoef_kernel(
    const int* __restrict__ ent_tokens,     // [E,T]
    const int* __restrict__ types,          // [B,E]
    const float* __restrict__ conf) {       // [B,E]
    __shared__ float sm[SS * 6];
    int b = blockIdx.x;
    int tid = threadIdx.x;                  // 0..511 == flat (e,t)

#pragma unroll
    for (int j = 0; j < 6; j++) sm[tid + j * SS] = 0.f;
    __syncthreads();

    int tok = ent_tokens[tid];
    int e = tid >> 2;
    int ty = types[b * EE + e];
    float c = conf[b * EE + e];
    atomicAdd(&sm[tok * 6 + ty], 1.f);
    atomicAdd(&sm[tok * 6 + 5], c);
    __syncthreads();

    float4* o = reinterpret_cast<float4*>(&g_rowcoef[((size_t)b * SS + tid) * 8]);
    o[0] = make_float4(sm[tid * 6 + 0], sm[tid * 6 + 1], sm[tid * 6 + 2], sm[tid * 6 + 3]);
    o[1] = make_float4(sm[tid * 6 + 4], sm[tid * 6 + 5], 0.f, 0.f);
}

// ---------------------------------------------------------------------------
// Fused main kernel (persistent grid-stride, SINGLE task per iteration — the
// R3 structure that measured best — but with the per-lane table cache moved
// from 24 registers into shared memory to raise occupancy 54.6% -> ~75%).
// Task list per batch b: 512 enhance rows then 128 emb tasks (computed from
// hidden directly, so gather reads hit L2 from the just-streamed batch rows).
// ---------------------------------------------------------------------------
__global__ void __launch_bounds__(H4, 8) fused_kernel(
    const float* __restrict__ hidden,       // [B,S,H]
    const int* __restrict__ ent_tokens,     // [E,T]
    const float* __restrict__ type_table,   // [NT,H]
    const float* __restrict__ conf_w,       // [H]
    const float* __restrict__ conf_b,       // [H]
    float* __restrict__ out_enh,            // [B,S,H]
    float* __restrict__ out_emb) {          // [B,E,H]
    __shared__ float4 s_tab[NT + 1][H4];    // [0..4]=type_table+conf_b, [5]=conf_w
    int tid = threadIdx.x;                  // 0..191
    int h = tid * 4;

    {
        float4 cb4 = *reinterpret_cast<const float4*>(conf_b + h);
        s_tab[NT][tid] = *reinterpret_cast<const float4*>(conf_w + h);
#pragma unroll
        for (int ty = 0; ty < NT; ty++) {
            float4 v = *reinterpret_cast<const float4*>(type_table + ty * HH + h);
            s_tab[ty][tid] = make_float4(v.x + cb4.x, v.y + cb4.y, v.z + cb4.z, v.w + cb4.w);
        }
    }
    __syncthreads();

    const int NTASK = BB * (SS + EE);
    for (int idx = blockIdx.x; idx < NTASK; idx += gridDim.x) {
        int b = idx / (SS + EE);
        int r = idx - b * (SS + EE);
        const float* hb = hidden + (size_t)b * SS * HH;

        if (r < SS) {
            // ---- enhance row (b, s=r) ----
            int s = r;
            const float4* cf = reinterpret_cast<const float4*>(
                &g_rowcoef[((size_t)b * SS + s) * 8]);
            float4 c0 = __ldg(cf);
            float4 c1 = __ldg(cf + 1);
            float4 v = *reinterpret_cast<const float4*>(hb + (size_t)s * HH + h);
            float a0 = c0.x, a1 = c0.y, a2 = c0.z, a3 = c0.w, a4 = c1.x, ac = c1.y;
            float4 t;
            t = s_tab[0][tid]; v.x += a0 * t.x; v.y += a0 * t.y; v.z += a0 * t.z; v.w += a0 * t.w;
            t = s_tab[1][tid]; v.x += a1 * t.x; v.y += a1 * t.y; v.z += a1 * t.z; v.w += a1 * t.w;
            t = s_tab[2][tid]; v.x += a2 * t.x; v.y += a2 * t.y; v.z += a2 * t.z; v.w += a2 * t.w;
            t = s_tab[3][tid]; v.x += a3 * t.x; v.y += a3 * t.y; v.z += a3 * t.z; v.w += a3 * t.w;
            t = s_tab[4][tid]; v.x += a4 * t.x; v.y += a4 * t.y; v.z += a4 * t.z; v.w += a4 * t.w;
            t = s_tab[5][tid]; v.x += ac * t.x; v.y += ac * t.y; v.z += ac * t.z; v.w += ac * t.w;
            *reinterpret_cast<float4*>(out_enh + ((size_t)b * SS + s) * HH + h) = v;
        } else {
            // ---- entity embedding (b, e): 0.25 * sum_t enhanced[b, tok, :] ----
            int e = r - SS;
            float4 acc = make_float4(0.f, 0.f, 0.f, 0.f);
            float a0 = 0.f, a1 = 0.f, a2 = 0.f, a3 = 0.f, a4 = 0.f, ac = 0.f;
#pragma unroll
            for (int t = 0; t < TT_; t++) {
                int s = __ldg(&ent_tokens[e * TT_ + t]);
                const float4* cf = reinterpret_cast<const float4*>(
                    &g_rowcoef[((size_t)b * SS + s) * 8]);
                float4 c0 = __ldg(cf);
                float4 c1 = __ldg(cf + 1);
                a0 += c0.x; a1 += c0.y; a2 += c0.z; a3 += c0.w; a4 += c1.x; ac += c1.y;
                float4 v = *reinterpret_cast<const float4*>(hb + (size_t)s * HH + h);
                acc.x += v.x; acc.y += v.y; acc.z += v.z; acc.w += v.w;
            }
            float4 t;
            t = s_tab[0][tid]; acc.x += a0 * t.x; acc.y += a0 * t.y; acc.z += a0 * t.z; acc.w += a0 * t.w;
            t = s_tab[1][tid]; acc.x += a1 * t.x; acc.y += a1 * t.y; acc.z += a1 * t.z; acc.w += a1 * t.w;
            t = s_tab[2][tid]; acc.x += a2 * t.x; acc.y += a2 * t.y; acc.z += a2 * t.z; acc.w += a2 * t.w;
            t = s_tab[3][tid]; acc.x += a3 * t.x; acc.y += a3 * t.y; acc.z += a3 * t.z; acc.w += a3 * t.w;
            t = s_tab[4][tid]; acc.x += a4 * t.x; acc.y += a4 * t.y; acc.z += a4 * t.z; acc.w += a4 * t.w;
            t = s_tab[5][tid]; acc.x += ac * t.x; acc.y += ac * t.y; acc.z += ac * t.z; acc.w += ac * t.w;
            acc.x *= 0.25f; acc.y *= 0.25f; acc.z *= 0.25f; acc.w *= 0.25f;
            *reinterpret_cast<float4*>(out_emb + ((size_t)b * EE + e) * HH + h) = acc;
        }
    }
}

// ---------------------------------------------------------------------------
// Inputs in metadata order:
// 0 hidden_states (B,S,H) f32 | 1 entity_types (B,E) i32 | 2 entity_confidences (B,E) f32
// 3 ent_tokens (E,T) i32 | 4 type_table (NT,H) f32 | 5 conf_w (1,H) f32 | 6 conf_b (H) f32
// Output: enhanced (B,S,H) then entity_embeddings (B,E,H), concatenated.
// ---------------------------------------------------------------------------
extern "C" void kernel_launch(void* const* d_in, const int* in_sizes, int n_in,
                              void* d_out, int out_size) {
    const float* hidden   = (const float*)d_in[0];
    const int*   types    = (const int*)d_in[1];
    const float* conf     = (const float*)d_in[2];
    const int*   ent_tok  = (const int*)d_in[3];
    const float* ttab     = (const float*)d_in[4];
    const float* conf_w   = (const float*)d_in[5];
    const float* conf_b   = (const float*)d_in[6];

    float* out_enh = (float*)d_out;
    float* out_emb = out_enh + (size_t)BB * SS * HH;

    rowcoef_kernel<<<BB, 512>>>(ent_tok, types, conf);
    fused_kernel<<<1184, H4>>>(hidden, ent_tok, ttab, conf_w, conf_b,
                               out_enh, out_emb);
}

// round 6
// speedup vs baseline: 1.7123x; 1.1649x over previous
#include <cuda_runtime.h>
#include <cstdint>

// Problem constants
#define BB 64
#define SS 512
#define HH 768
#define EE 128
#define TT_ 4
#define NT 5
#define H4 192   // H/4 float4 lanes

// Scratch (no allocs allowed)
__device__ float g_rowcoef[BB * SS * 8];   // {at0..at4, ac, 0, 0} per (b,s)

// ---------------------------------------------------------------------------
// P: per-batch coefficient build. One block per batch b (512 threads, one per
// flat (e,t)). Histogram into smem via atomics, then write 512 rows x 8 floats.
// ---------------------------------------------------------------------------
__global__ void __launch_bounds__(512) rowcoef_kernel(
    const int* __restrict__ ent_tokens,     // [E,T]
    const int* __restrict__ types,          // [B,E]
    const float* __restrict__ conf) {       // [B,E]
    __shared__ float sm[SS * 6];
    int b = blockIdx.x;
    int tid = threadIdx.x;                  // 0..511 == flat (e,t)

#pragma unroll
    for (int j = 0; j < 6; j++) sm[tid + j * SS] = 0.f;
    __syncthreads();

    int tok = ent_tokens[tid];
    int e = tid >> 2;
    int ty = types[b * EE + e];
    float c = conf[b * EE + e];
    atomicAdd(&sm[tok * 6 + ty], 1.f);
    atomicAdd(&sm[tok * 6 + 5], c);
    __syncthreads();

    float4* o = reinterpret_cast<float4*>(&g_rowcoef[((size_t)b * SS + tid) * 8]);
    o[0] = make_float4(sm[tid * 6 + 0], sm[tid * 6 + 1], sm[tid * 6 + 2], sm[tid * 6 + 3]);
    o[1] = make_float4(sm[tid * 6 + 4], sm[tid * 6 + 5], 0.f, 0.f);
}

// ---------------------------------------------------------------------------
// Fused main kernel (persistent grid-stride, smem tables for occupancy).
// Enhance path exploits block-uniform coefficient sparsity:
//   - all-zero coef row (~37%): straight copy, zero LDS/FMA
//   - else loop only over nonzero type buckets (~1-2 of 5) — uniform branches
// Emb tasks computed directly from hidden + coefficients (L2-hot gather).
// ---------------------------------------------------------------------------
__global__ void __launch_bounds__(H4, 8) fused_kernel(
    const float* __restrict__ hidden,       // [B,S,H]
    const int* __restrict__ ent_tokens,     // [E,T]
    const float* __restrict__ type_table,   // [NT,H]
    const float* __restrict__ conf_w,       // [H]
    const float* __restrict__ conf_b,       // [H]
    float* __restrict__ out_enh,            // [B,S,H]
    float* __restrict__ out_emb) {          // [B,E,H]
    __shared__ float4 s_tab[NT + 1][H4];    // [0..4]=type_table+conf_b, [5]=conf_w
    int tid = threadIdx.x;                  // 0..191
    int h = tid * 4;

    {
        float4 cb4 = *reinterpret_cast<const float4*>(conf_b + h);
        s_tab[NT][tid] = *reinterpret_cast<const float4*>(conf_w + h);
#pragma unroll
        for (int ty = 0; ty < NT; ty++) {
            float4 v = *reinterpret_cast<const float4*>(type_table + ty * HH + h);
            s_tab[ty][tid] = make_float4(v.x + cb4.x, v.y + cb4.y, v.z + cb4.z, v.w + cb4.w);
        }
    }
    __syncthreads();

    const int NTASK = BB * (SS + EE);
    for (int idx = blockIdx.x; idx < NTASK; idx += gridDim.x) {
        int b = idx / (SS + EE);
        int r = idx - b * (SS + EE);
        const float* hb = hidden + (size_t)b * SS * HH;

        if (r < SS) {
            // ---- enhance row (b, s=r) ----
            int s = r;
            const float4* cf = reinterpret_cast<const float4*>(
                &g_rowcoef[((size_t)b * SS + s) * 8]);
            float4 c0 = __ldg(cf);
            float4 c1 = __ldg(cf + 1);
            float4 v = *reinterpret_cast<const float4*>(hb + (size_t)s * HH + h);
            // block-uniform sparsity: skip work for empty rows / zero buckets
            float a[NT + 1] = {c0.x, c0.y, c0.z, c0.w, c1.x, c1.y};
            bool any = (c0.x != 0.f) | (c0.y != 0.f) | (c0.z != 0.f) |
                       (c0.w != 0.f) | (c1.x != 0.f) | (c1.y != 0.f);
            if (any) {
#pragma unroll
                for (int j = 0; j < NT + 1; j++) {
                    if (a[j] != 0.f) {      // uniform across block
                        float4 t = s_tab[j][tid];
                        v.x += a[j] * t.x; v.y += a[j] * t.y;
                        v.z += a[j] * t.z; v.w += a[j] * t.w;
                    }
                }
            }
            *reinterpret_cast<float4*>(out_enh + ((size_t)b * SS + s) * HH + h) = v;
        } else {
            // ---- entity embedding (b, e): 0.25 * sum_t enhanced[b, tok, :] ----
            int e = r - SS;
            float4 acc = make_float4(0.f, 0.f, 0.f, 0.f);
            float a0 = 0.f, a1 = 0.f, a2 = 0.f, a3 = 0.f, a4 = 0.f, ac = 0.f;
#pragma unroll
            for (int t = 0; t < TT_; t++) {
                int s = __ldg(&ent_tokens[e * TT_ + t]);
                const float4* cf = reinterpret_cast<const float4*>(
                    &g_rowcoef[((size_t)b * SS + s) * 8]);
                float4 c0 = __ldg(cf);
                float4 c1 = __ldg(cf + 1);
                a0 += c0.x; a1 += c0.y; a2 += c0.z; a3 += c0.w; a4 += c1.x; ac += c1.y;
                float4 v = *reinterpret_cast<const float4*>(hb + (size_t)s * HH + h);
                acc.x += v.x; acc.y += v.y; acc.z += v.z; acc.w += v.w;
            }
            float4 t;
            t = s_tab[0][tid]; acc.x += a0 * t.x; acc.y += a0 * t.y; acc.z += a0 * t.z; acc.w += a0 * t.w;
            t = s_tab[1][tid]; acc.x += a1 * t.x; acc.y += a1 * t.y; acc.z += a1 * t.z; acc.w += a1 * t.w;
            t = s_tab[2][tid]; acc.x += a2 * t.x; acc.y += a2 * t.y; acc.z += a2 * t.z; acc.w += a2 * t.w;
            t = s_tab[3][tid]; acc.x += a3 * t.x; acc.y += a3 * t.y; acc.z += a3 * t.z; acc.w += a3 * t.w;
            t = s_tab[4][tid]; acc.x += a4 * t.x; acc.y += a4 * t.y; acc.z += a4 * t.z; acc.w += a4 * t.w;
            t = s_tab[5][tid]; acc.x += ac * t.x; acc.y += ac * t.y; acc.z += ac * t.z; acc.w += ac * t.w;
            acc.x *= 0.25f; acc.y *= 0.25f; acc.z *= 0.25f; acc.w *= 0.25f;
            *reinterpret_cast<float4*>(out_emb + ((size_t)b * EE + e) * HH + h) = acc;
        }
    }
}

// ---------------------------------------------------------------------------
// Inputs in metadata order:
// 0 hidden_states (B,S,H) f32 | 1 entity_types (B,E) i32 | 2 entity_confidences (B,E) f32
// 3 ent_tokens (E,T) i32 | 4 type_table (NT,H) f32 | 5 conf_w (1,H) f32 | 6 conf_b (H) f32
// Output: enhanced (B,S,H) then entity_embeddings (B,E,H), concatenated.
// ---------------------------------------------------------------------------
extern "C" void kernel_launch(void* const* d_in, const int* in_sizes, int n_in,
                              void* d_out, int out_size) {
    const float* hidden   = (const float*)d_in[0];
    const int*   types    = (const int*)d_in[1];
    const float* conf     = (const float*)d_in[2];
    const int*   ent_tok  = (const int*)d_in[3];
    const float* ttab     = (const float*)d_in[4];
    const float* conf_w   = (const float*)d_in[5];
    const float* conf_b   = (const float*)d_in[6];

    float* out_enh = (float*)d_out;
    float* out_emb = out_enh + (size_t)BB * SS * HH;

    rowcoef_kernel<<<BB, 512>>>(ent_tok, types, conf);
    fused_kernel<<<1184, H4>>>(hidden, ent_tok, ttab, conf_w, conf_b,
                               out_enh, out_emb);
}